// round 7
// baseline (speedup 1.0000x reference)
#include <cuda_runtime.h>
#include <math.h>
#include <stdint.h>

// out[i] = sum_{j<512} r[batch[i][j]] + log(n_pos / n_neg)
//
// r (201KB) staged in SMEM via TMA. Index rows ALSO streamed via TMA into
// two 7-row SMEM buffers (bypasses the LDG/MSHR path, which capped at
// ~2.6TB/s). Producer warp issues bulk copies; 14 consumer warps gather.
// CTA b owns contiguous rows [start_b, start_b + cnt_b), cnt = 110/111.

#define ROWS   16384
#define LEN    512
#define VOCAB  50257
#define NBLK   148
#define NTHR   512
#define TROWS  7
#define NTILES 16                       // ceil(111/7) = ceil(110/7) = 16
#define ROW_BYTES (LEN * 4)             // 2048

#define RS_BYTES (VOCAB * 4)            // 201028
#define RS_BULK  ((RS_BYTES / 16) * 16) // 201024

#define BAR_OFF   201040                // 16B aligned, after rs
#define R_BAR     (BAR_OFF + 0)
#define FULL_B(g)  (BAR_OFF + 8  + (g) * 8)
#define EMPTY_B(g) (BAR_OFF + 24 + (g) * 8)
#define BUF_OFF(g) (201088 + (g) * TROWS * ROW_BYTES)
#define SMEM_TOTAL (201088 + 2 * TROWS * ROW_BYTES)   // 229760 <= 232448

__device__ __forceinline__ uint32_t smem_u32(const void* p) {
    uint32_t a;
    asm("{ .reg .u64 t; cvta.to.shared.u64 t, %1; cvt.u32.u64 %0, t; }"
        : "=r"(a) : "l"(p));
    return a;
}

__device__ __forceinline__ void bar_init(uint32_t bar, uint32_t cnt) {
    asm volatile("mbarrier.init.shared.b64 [%0], %1;" :: "r"(bar), "r"(cnt) : "memory");
}
__device__ __forceinline__ void bar_arrive(uint32_t bar) {
    asm volatile("mbarrier.arrive.release.cta.shared::cta.b64 _, [%0];" :: "r"(bar) : "memory");
}
__device__ __forceinline__ void bar_expect_tx(uint32_t bar, uint32_t bytes) {
    asm volatile("mbarrier.arrive.expect_tx.shared.b64 _, [%0], %1;"
                 :: "r"(bar), "r"(bytes) : "memory");
}
__device__ __forceinline__ void bar_wait(uint32_t bar, uint32_t parity) {
    uint32_t done;
    asm volatile(
        "{ .reg .pred p;\n"
        "  mbarrier.try_wait.parity.acquire.cta.shared::cta.b64 p, [%1], %2;\n"
        "  selp.b32 %0, 1, 0, p; }"
        : "=r"(done) : "r"(bar), "r"(parity) : "memory");
    if (!done) {
        asm volatile(
            "{ .reg .pred P1;\n"
            "W_LOOP:\n"
            "  mbarrier.try_wait.parity.acquire.cta.shared::cta.b64 P1, [%0], %1, 0x989680;\n"
            "  @P1 bra.uni W_DONE;\n"
            "  bra.uni W_LOOP;\n"
            "W_DONE: }"
            :: "r"(bar), "r"(parity) : "memory");
    }
}
__device__ __forceinline__ void bulk_g2s(uint32_t dst, const void* src,
                                         uint32_t bytes, uint32_t bar) {
    asm volatile(
        "cp.async.bulk.shared::cta.global.mbarrier::complete_tx::bytes "
        "[%0], [%1], %2, [%3];"
        :: "r"(dst), "l"(src), "r"(bytes), "r"(bar) : "memory");
}

__global__ __launch_bounds__(NTHR, 1) void nb_tma2_kernel(
    const int* __restrict__ batch,
    const float* __restrict__ r,
    const int* __restrict__ n_pos,
    const int* __restrict__ n_neg,
    float* __restrict__ out)
{
    extern __shared__ float rs[];
    char* sm = reinterpret_cast<char*>(rs);

    const int tid  = threadIdx.x;
    const int warp = tid >> 5;
    const int lane = tid & 31;
    const int b    = blockIdx.x;

    const int cnt   = 110 + (b < 104);
    const int start = b * 110 + (b < 104 ? b : 104);

    const uint32_t rs_s    = smem_u32(sm);
    const uint32_t rbar    = smem_u32(sm + R_BAR);
    const uint32_t fullb0  = smem_u32(sm + FULL_B(0));
    const uint32_t fullb1  = smem_u32(sm + FULL_B(1));
    const uint32_t emptyb0 = smem_u32(sm + EMPTY_B(0));
    const uint32_t emptyb1 = smem_u32(sm + EMPTY_B(1));

    if (tid == 0) {
        rs[VOCAB - 1] = r[VOCAB - 1];        // 4B tail TMA can't cover
        bar_init(rbar, 1);
        bar_init(fullb0, 1);  bar_init(fullb1, 1);
        bar_init(emptyb0, 7); bar_init(emptyb1, 7);
    }
    __syncthreads();

    // ---------------- Producer: warp 15, lane 0 ----------------
    if (warp == 15) {
        if (lane == 0) {
            // Stage r (4 chunks, one tx budget).
            bar_expect_tx(rbar, (uint32_t)RS_BULK);
            const uint32_t chunk = RS_BULK / 4;
#pragma unroll
            for (int i = 0; i < 4; i++)
                bulk_g2s(rs_s + i * chunk, (const char*)r + i * chunk, chunk, rbar);

            // Stream 16 index tiles, alternating buffers.
            int kk0 = 0, kk1 = 0;
#pragma unroll 1
            for (int t = 0; t < NTILES; t++) {
                const int g = t & 1;
                const uint32_t fb = g ? fullb1 : fullb0;
                const uint32_t eb = g ? emptyb1 : emptyb0;
                int& kk = g ? kk1 : kk0;
                if (kk > 0)
                    bar_wait(eb, (kk - 1) & 1);
                int rows = cnt - t * TROWS;
                if (rows > TROWS) rows = TROWS;
                const uint32_t bytes = (uint32_t)rows * ROW_BYTES;
                bar_expect_tx(fb, bytes);
                bulk_g2s(smem_u32(sm + BUF_OFF(g)),
                         (const char*)batch + (size_t)(start + t * TROWS) * ROW_BYTES,
                         bytes, fb);
                kk++;
            }
        }
        return;
    }
    if (warp == 7) return;   // idle warp

    // ---------------- Consumers: warps 0-6 (buf 0), 8-14 (buf 1) ----------------
    const int g  = (warp < 7) ? 0 : 1;
    const int lw = (warp < 7) ? warp : warp - 8;     // row within tile
    const uint32_t fb = g ? fullb1 : fullb0;
    const uint32_t eb = g ? emptyb1 : emptyb0;
    const int4* __restrict__ bp =
        reinterpret_cast<const int4*>(sm + BUF_OFF(g) + lw * ROW_BYTES);

    const float lp = logf((float)__ldg(n_pos) / (float)__ldg(n_neg));

    bar_wait(rbar, 0);       // r must be resident before first gather

#pragma unroll 1
    for (int k = 0; k < NTILES / 2; k++) {
        const int t = 2 * k + g;
        bar_wait(fb, k & 1);

        const int rl    = t * TROWS + lw;
        const bool valid = rl < cnt;      // uniform across the warp
        float s = 0.0f;
        if (valid) {
            float a = 0.f, c = 0.f;
#pragma unroll
            for (int i = 0; i < 4; i++) {
                int4 v = bp[lane + 32 * i];
                a += rs[v.x];  c += rs[v.y];
                a += rs[v.z];  c += rs[v.w];
            }
            s = a + c;
#pragma unroll
            for (int o = 16; o > 0; o >>= 1)
                s += __shfl_xor_sync(0xFFFFFFFFu, s, o);
        }
        __syncwarp();
        if (lane == 0) {
            bar_arrive(eb);
            if (valid) out[start + rl] = s + lp;
        }
    }
}

extern "C" void kernel_launch(void* const* d_in, const int* in_sizes, int n_in,
                              void* d_out, int out_size)
{
    const int*   batch = (const int*)  d_in[0];
    const float* r     = (const float*)d_in[1];
    const int*   npos  = (const int*)  d_in[2];
    const int*   nneg  = (const int*)  d_in[3];
    float*       out   = (float*)      d_out;

    static int configured = 0;
    if (!configured) {
        cudaFuncSetAttribute(nb_tma2_kernel,
                             cudaFuncAttributeMaxDynamicSharedMemorySize,
                             SMEM_TOTAL);
        configured = 1;
    }

    nb_tma2_kernel<<<NBLK, NTHR, SMEM_TOTAL>>>(batch, r, npos, nneg, out);
}

// round 8
// speedup vs baseline: 1.1805x; 1.1805x over previous
#include <cuda_runtime.h>
#include <math.h>
#include <stdint.h>

// out[i] = sum_{j<512} r[batch[i][j]] + log(n_pos / n_neg)
//
// r (201KB) staged into SMEM via TMA *multicast* over a 2-CTA cluster:
// each CTA bulk-loads half of r and multicasts it to both CTAs, halving
// the chip-wide L2 staging traffic (29.7MB -> 14.9MB). Meanwhile every
// warp pre-issues all six of its index rows (24 LDG.128 in flight).
// 148 CTAs (74 clusters) x 512 threads.

#define ROWS   16384
#define LEN    512
#define VOCAB  50257
#define NBLK   148
#define NTHR   512
#define NWARP  (NTHR / 32)           // 16
#define GWARPS (NBLK * NWARP)        // 2368;  ROWS = 6*GWARPS + 2176

#define RS_BYTES   (VOCAB * 4)               // 201028
#define RS_BULK    ((RS_BYTES / 16) * 16)    // 201024
#define RS_HALF    (RS_BULK / 2)             // 100512 (16B multiple)
#define RS_CHUNK   (RS_HALF / 2)             // 50256  (16B multiple)
#define MBAR_OFF   201040
#define SMEM_TOTAL (MBAR_OFF + 16)

__device__ __forceinline__ uint32_t smem_u32(const void* p) {
    uint32_t a;
    asm("{ .reg .u64 t; cvta.to.shared.u64 t, %1; cvt.u32.u64 %0, t; }"
        : "=r"(a) : "l"(p));
    return a;
}

__device__ __forceinline__ void load_row(const int* __restrict__ batch,
                                         int row, int lane, int4* v)
{
    const int4* __restrict__ bp =
        reinterpret_cast<const int4*>(batch + (size_t)row * LEN);
#pragma unroll
    for (int i = 0; i < 4; i++)
        v[i] = bp[lane + 32 * i];
}

__device__ __forceinline__ void compute_pair(const float* __restrict__ rs,
                                             const int4* x, const int4* y,
                                             int lane, float lp,
                                             float* __restrict__ out,
                                             int row0, int row1)
{
    float a0 = 0.f, b0 = 0.f, a1 = 0.f, b1 = 0.f;
#pragma unroll
    for (int i = 0; i < 4; i++) {
        a0 += rs[x[i].x];  b0 += rs[x[i].y];
        a0 += rs[x[i].z];  b0 += rs[x[i].w];
        a1 += rs[y[i].x];  b1 += rs[y[i].y];
        a1 += rs[y[i].z];  b1 += rs[y[i].w];
    }
    float s0 = a0 + b0;
    float s1 = a1 + b1;
#pragma unroll
    for (int o = 16; o > 0; o >>= 1) {
        s0 += __shfl_xor_sync(0xFFFFFFFFu, s0, o);
        s1 += __shfl_xor_sync(0xFFFFFFFFu, s1, o);
    }
    if (lane == 0) {
        out[row0] = s0 + lp;
        out[row1] = s1 + lp;
    }
}

__global__ __launch_bounds__(NTHR, 1) __cluster_dims__(2, 1, 1)
void nb_mc_kernel(
    const int* __restrict__ batch,
    const float* __restrict__ r,
    const int* __restrict__ n_pos,
    const int* __restrict__ n_neg,
    float* __restrict__ out)
{
    extern __shared__ float rs[];
    const int tid  = threadIdx.x;
    const int warp = tid >> 5;
    const int lane = tid & 31;
    const int gw   = blockIdx.x * NWARP + warp;

    char* smem_raw = reinterpret_cast<char*>(rs);
    const uint32_t mbar = smem_u32(smem_raw + MBAR_OFF);
    const uint32_t rs_s = smem_u32(smem_raw);

    uint32_t rank;
    asm("mov.u32 %0, %%cluster_ctarank;" : "=r"(rank));

    if (tid == 0) {
        rs[VOCAB - 1] = r[VOCAB - 1];    // 4B tail TMA can't cover
        asm volatile("mbarrier.init.shared.b64 [%0], %1;" :: "r"(mbar), "r"(1) : "memory");
    }
    __syncthreads();

    // Both CTAs' barriers must be initialized before any peer multicast lands.
    asm volatile("barrier.cluster.arrive.aligned;" ::: "memory");
    asm volatile("barrier.cluster.wait.aligned;"   ::: "memory");

    // ---- Multicast staging: this CTA loads its half of r to BOTH CTAs ----
    if (tid == 0) {
        asm volatile("mbarrier.arrive.expect_tx.shared.b64 _, [%0], %1;"
                     :: "r"(mbar), "r"((uint32_t)RS_BULK) : "memory");
        const uint32_t base = rank * (uint32_t)RS_HALF;
#pragma unroll
        for (int i = 0; i < 2; i++) {
            const uint32_t off = base + i * (uint32_t)RS_CHUNK;
            asm volatile(
                "cp.async.bulk.shared::cluster.global.mbarrier::complete_tx::bytes"
                ".multicast::cluster [%0], [%1], %2, [%3], %4;"
                :: "r"(rs_s + off),
                   "l"((const char*)r + off),
                   "r"((uint32_t)RS_CHUNK),
                   "r"(mbar),
                   "h"((uint16_t)0x3)
                : "memory");
        }
    }

    // ---- Pre-issue ALL six rows' index loads (24 LDG.128 per warp) ----
    int4 A[4], B[4], C[4], D[4], E[4], F[4];
    load_row(batch, gw + 0 * GWARPS, lane, A);
    load_row(batch, gw + 1 * GWARPS, lane, B);
    load_row(batch, gw + 2 * GWARPS, lane, C);
    load_row(batch, gw + 3 * GWARPS, lane, D);
    load_row(batch, gw + 4 * GWARPS, lane, E);
    load_row(batch, gw + 5 * GWARPS, lane, F);
    const bool has7 = (gw + 6 * GWARPS) < ROWS;   // gw < 2176

    const float lp = logf((float)__ldg(n_pos) / (float)__ldg(n_neg));

    // ---- Wait for r (acquire): tx from own half + peer's multicast half ----
    {
        uint32_t done;
        asm volatile(
            "{ .reg .pred p;\n"
            "  mbarrier.try_wait.parity.acquire.cta.shared::cta.b64 p, [%1], %2;\n"
            "  selp.b32 %0, 1, 0, p; }"
            : "=r"(done) : "r"(mbar), "r"(0u) : "memory");
        if (!done) {
            asm volatile(
                "{ .reg .pred P1;\n"
                "WAIT_LOOP:\n"
                "  mbarrier.try_wait.parity.acquire.cta.shared::cta.b64 P1, [%0], %1, 0x989680;\n"
                "  @P1 bra.uni WAIT_DONE;\n"
                "  bra.uni WAIT_LOOP;\n"
                "WAIT_DONE: }"
                :: "r"(mbar), "r"(0u) : "memory");
        }
    }

    // ---- Compute: three pairs + optional 7th row ----
    compute_pair(rs, A, B, lane, lp, out, gw + 0 * GWARPS, gw + 1 * GWARPS);

    int4 G[4];
    if (has7) load_row(batch, gw + 6 * GWARPS, lane, G);

    compute_pair(rs, C, D, lane, lp, out, gw + 2 * GWARPS, gw + 3 * GWARPS);
    compute_pair(rs, E, F, lane, lp, out, gw + 4 * GWARPS, gw + 5 * GWARPS);

    if (has7) {
        float a = 0.f, b = 0.f;
#pragma unroll
        for (int i = 0; i < 4; i++) {
            a += rs[G[i].x];  b += rs[G[i].y];
            a += rs[G[i].z];  b += rs[G[i].w];
        }
        float s = a + b;
#pragma unroll
        for (int o = 16; o > 0; o >>= 1)
            s += __shfl_xor_sync(0xFFFFFFFFu, s, o);
        if (lane == 0)
            out[gw + 6 * GWARPS] = s + lp;
    }

    // No CTA may exit while its SMEM could still receive peer multicast —
    // all tx landed before compute (we waited), but keep exit symmetric.
    asm volatile("barrier.cluster.arrive.aligned;" ::: "memory");
    asm volatile("barrier.cluster.wait.aligned;"   ::: "memory");
}

extern "C" void kernel_launch(void* const* d_in, const int* in_sizes, int n_in,
                              void* d_out, int out_size)
{
    const int*   batch = (const int*)  d_in[0];
    const float* r     = (const float*)d_in[1];
    const int*   npos  = (const int*)  d_in[2];
    const int*   nneg  = (const int*)  d_in[3];
    float*       out   = (float*)      d_out;

    static int configured = 0;
    if (!configured) {
        cudaFuncSetAttribute(nb_mc_kernel,
                             cudaFuncAttributeMaxDynamicSharedMemorySize,
                             SMEM_TOTAL);
        configured = 1;
    }

    nb_mc_kernel<<<NBLK, NTHR, SMEM_TOTAL>>>(batch, r, npos, nneg, out);
}